// round 9
// baseline (speedup 1.0000x reference)
#include <cuda_runtime.h>
#include <cuda_fp16.h>
#include <cstdint>

// ---------------------------------------------------------------------------
// y[8192,16384] = x[8192,4096] @ dequant(W[4096,16384]) * scale + bias
// Weight arrives as int32 (harness dtype set is f32/i32/bf16).
// R9: software-pipelined fragments (ldmatrix for ks+1 issued before MMAs of ks)
//     on top of R8's 128x128 tile / 128 threads / 3-stage BK=64 / 2 CTAs/SM.
// ---------------------------------------------------------------------------
static constexpr int M_ROWS = 8192;
static constexpr int K_DIM  = 4096;
static constexpr int N_DIM  = 16384;

static constexpr int BM = 128;
static constexpr int BN = 128;
static constexpr int BK = 64;
static constexpr int STAGES = 3;
static constexpr int NITER  = K_DIM / BK;     // 64
static constexpr int KSTEPS = BK / 16;        // 4

static constexpr int A_LD = BK + 8;           // 72 halves = 144 B
static constexpr int B_LD = BK + 8;
static constexpr int A_ST = BM * A_LD;        // 9216 halves
static constexpr int B_ST = BN * B_LD;        // 9216 halves
static constexpr int STG  = A_ST + B_ST;      // 18432 halves = 36864 B
static constexpr int SMEM_BYTES = STAGES * STG * 2;   // 110592 B -> 2 CTAs/SM

__device__ __half g_xh[(size_t)M_ROWS * K_DIM];   //  64 MiB  [M][K]
__device__ __half g_wh[(size_t)N_DIM * K_DIM];    // 128 MiB  [N][K]

// ---------------------------------------------------------------------------
__device__ __forceinline__ uint32_t smem_u32(const void* p) {
    uint32_t a;
    asm("{ .reg .u64 t; cvta.to.shared.u64 t, %1; cvt.u32.u64 %0, t; }" : "=r"(a) : "l"(p));
    return a;
}

__device__ __forceinline__ void cp16(uint32_t dst, const void* src) {
    asm volatile("cp.async.cg.shared.global [%0], [%1], 16;" :: "r"(dst), "l"(src));
}

#define CP_COMMIT() asm volatile("cp.async.commit_group;" ::: "memory")

__device__ __forceinline__ void ldsm4(uint32_t* r, uint32_t addr) {
    asm volatile("ldmatrix.sync.aligned.m8n8.x4.shared.b16 {%0,%1,%2,%3}, [%4];"
                 : "=r"(r[0]), "=r"(r[1]), "=r"(r[2]), "=r"(r[3]) : "r"(addr));
}

__device__ __forceinline__ void mma16816(float* d, const uint32_t* a, uint32_t b0, uint32_t b1) {
    asm volatile(
        "mma.sync.aligned.m16n8k16.row.col.f32.f16.f16.f32 "
        "{%0,%1,%2,%3}, {%4,%5,%6,%7}, {%8,%9}, {%0,%1,%2,%3};"
        : "+f"(d[0]), "+f"(d[1]), "+f"(d[2]), "+f"(d[3])
        : "r"(a[0]), "r"(a[1]), "r"(a[2]), "r"(a[3]), "r"(b0), "r"(b1));
}

// ---------------------------------------------------------------------------
// Prep kernels
// ---------------------------------------------------------------------------
__global__ void cvt_x_kernel(const float4* __restrict__ x, __half2* __restrict__ out, int n4) {
    int i = blockIdx.x * blockDim.x + threadIdx.x;
    if (i < n4) {
        float4 v = x[i];
        out[2 * i]     = __floats2half2_rn(v.x, v.y);
        out[2 * i + 1] = __floats2half2_rn(v.z, v.w);
    }
}

// W[k][n] int32 row-major -> Wh[n][k] fp16 (exact), 32x32 smem transpose
__global__ void cvt_w_kernel(const int* __restrict__ w, __half* __restrict__ out) {
    __shared__ int t[32][33];
    int n0 = blockIdx.x * 32, k0 = blockIdx.y * 32;
    int tx = threadIdx.x, ty = threadIdx.y;
    #pragma unroll
    for (int i = ty; i < 32; i += 8)
        t[i][tx] = w[(size_t)(k0 + i) * N_DIM + n0 + tx];
    __syncthreads();
    #pragma unroll
    for (int i = ty; i < 32; i += 8)
        out[(size_t)(n0 + i) * K_DIM + k0 + tx] = __int2half_rn(t[tx][i]);
}

// ---------------------------------------------------------------------------
// Main GEMM
// ---------------------------------------------------------------------------
__global__ void __launch_bounds__(128, 2) qgemm_kernel(
    const float* __restrict__ scale,
    const float* __restrict__ bias,
    float* __restrict__ out)
{
    extern __shared__ __align__(16) char smem_raw[];
    const uint32_t sb = smem_u32(smem_raw);
    const int tid = threadIdx.x;
    const int wid = tid >> 5;
    const int lid = tid & 31;

    const int bid = blockIdx.x;
    const int group  = bid >> 9;
    const int within = bid & 511;
    const int nt = (group << 3) | (within & 7);
    const int mt = within >> 3;
    const int m0 = mt * BM;
    const int n0 = nt * BN;

    const __half* __restrict__ xh = g_xh;
    const __half* __restrict__ wh = g_wh;

    auto issue_stage = [&](int it) {
        const int k0 = it * BK;
        const uint32_t base = sb + (uint32_t)(it % STAGES) * (STG * 2);
        #pragma unroll
        for (int j = 0; j < 8; ++j) {
            int ci = tid + 128 * j;
            int row = ci >> 3, cc = ci & 7;
            cp16(base + (uint32_t)(row * A_LD + cc * 8) * 2,
                 xh + (size_t)(m0 + row) * K_DIM + k0 + cc * 8);
        }
        #pragma unroll
        for (int j = 0; j < 8; ++j) {
            int ci = tid + 128 * j;
            int row = ci >> 3, cc = ci & 7;
            cp16(base + (uint32_t)(A_ST + row * B_LD + cc * 8) * 2,
                 wh + (size_t)(n0 + row) * K_DIM + k0 + cc * 8);
        }
        CP_COMMIT();
    };

    const int wmb = (wid & 1) * 64;
    const int wnb = (wid >> 1) * 64;

    float acc[4][8][4];
    #pragma unroll
    for (int i = 0; i < 4; ++i)
        #pragma unroll
        for (int j = 0; j < 8; ++j)
            #pragma unroll
            for (int k = 0; k < 4; ++k) acc[i][j][k] = 0.0f;

    issue_stage(0);
    issue_stage(1);

    const int a_row_lane = lid & 15;
    const int a_col_lane = (lid >> 4) * 8;
    const int b_row_lane = (lid & 7) | ((lid >> 4) << 3);
    const int b_col_lane = ((lid >> 3) & 1) * 8;

    // Per-warp fixed smem offsets (halves -> bytes at use site)
    const uint32_t a_off = (uint32_t)((wmb + a_row_lane) * A_LD + a_col_lane) * 2;
    const uint32_t b_off = (uint32_t)(A_ST + (wnb + b_row_lane) * B_LD + b_col_lane) * 2;

    // Fragment ping-pong buffers
    uint32_t a[2][4][4], b[2][4][4];

    auto load_frags = [&](uint32_t base, int ks, int buf) {
        #pragma unroll
        for (int mf = 0; mf < 4; ++mf)
            ldsm4(a[buf][mf], base + a_off + (uint32_t)(mf * 16 * A_LD + ks * 16) * 2);
        #pragma unroll
        for (int nf2 = 0; nf2 < 4; ++nf2)
            ldsm4(b[buf][nf2], base + b_off + (uint32_t)(nf2 * 16 * B_LD + ks * 16) * 2);
    };

    auto run_mmas = [&](int buf) {
        #pragma unroll
        for (int mf = 0; mf < 4; ++mf) {
            #pragma unroll
            for (int nf2 = 0; nf2 < 4; ++nf2) {
                mma16816(acc[mf][nf2 * 2],     a[buf][mf], b[buf][nf2][0], b[buf][nf2][1]);
                mma16816(acc[mf][nf2 * 2 + 1], a[buf][mf], b[buf][nf2][2], b[buf][nf2][3]);
            }
        }
    };

    #pragma unroll 1
    for (int it = 0; it < NITER; ++it) {
        asm volatile("cp.async.wait_group 1;" ::: "memory");
        __syncthreads();
        if (it + 2 < NITER) issue_stage(it + 2);
        else CP_COMMIT();

        const uint32_t base = sb + (uint32_t)(it % STAGES) * (STG * 2);
        load_frags(base, 0, 0);
        #pragma unroll
        for (int ks = 0; ks < KSTEPS; ++ks) {
            if (ks + 1 < KSTEPS) load_frags(base, ks + 1, (ks + 1) & 1);
            run_mmas(ks & 1);
        }
    }

    // ---- Epilogue: fused scale/bias, float2 stores ----
    const int ncol0 = n0 + wnb;
    float2 sc[8], bi[8];
    #pragma unroll
    for (int nf = 0; nf < 8; ++nf) {
        int c = nf * 8 + (lid & 3) * 2;
        sc[nf] = *reinterpret_cast<const float2*>(scale + ncol0 + c);
        bi[nf] = *reinterpret_cast<const float2*>(bias + ncol0 + c);
    }
    #pragma unroll
    for (int mf = 0; mf < 4; ++mf) {
        int r0 = m0 + wmb + mf * 16 + (lid >> 2);
        float* out0 = out + (size_t)r0 * N_DIM + ncol0;
        float* out1 = out0 + (size_t)8 * N_DIM;
        #pragma unroll
        for (int nf = 0; nf < 8; ++nf) {
            int c = nf * 8 + (lid & 3) * 2;
            float2 v0 = make_float2(fmaf(acc[mf][nf][0], sc[nf].x, bi[nf].x),
                                    fmaf(acc[mf][nf][1], sc[nf].y, bi[nf].y));
            float2 v1 = make_float2(fmaf(acc[mf][nf][2], sc[nf].x, bi[nf].x),
                                    fmaf(acc[mf][nf][3], sc[nf].y, bi[nf].y));
            *reinterpret_cast<float2*>(out0 + c) = v0;
            *reinterpret_cast<float2*>(out1 + c) = v1;
        }
    }
}

// ---------------------------------------------------------------------------
// Host launch — inputs identified by element count.
// ---------------------------------------------------------------------------
extern "C" void kernel_launch(void* const* d_in, const int* in_sizes, int n_in,
                              void* d_out, int out_size) {
    int xi = 0, wi = 1, sm1 = -1, sm2 = -1;
    for (int i = 0; i < 4; ++i) {
        if (in_sizes[i] == M_ROWS * K_DIM)      xi = i;
        else if (in_sizes[i] == K_DIM * N_DIM)  wi = i;
        else if (sm1 < 0)                       sm1 = i;
        else                                    sm2 = i;
    }
    int si, bi2;
    if (xi < sm1) { si = sm1; bi2 = sm2; }   // dict order: x, w, scale, bias
    else          { bi2 = sm1; si = sm2; }

    const float* x     = (const float*)d_in[xi];
    const int*   w     = (const int*)d_in[wi];
    const float* scale = (const float*)d_in[si];
    const float* bias  = (const float*)d_in[bi2];
    float*       out   = (float*)d_out;

    void* xh = nullptr; cudaGetSymbolAddress(&xh, g_xh);
    void* wh = nullptr; cudaGetSymbolAddress(&wh, g_wh);

    int nx4 = M_ROWS * K_DIM / 4;
    cvt_x_kernel<<<nx4 / 256, 256>>>((const float4*)x, (__half2*)xh, nx4);
    cvt_w_kernel<<<dim3(N_DIM / 32, K_DIM / 32), dim3(32, 8)>>>(w, (__half*)wh);

    cudaFuncSetAttribute(qgemm_kernel, cudaFuncAttributeMaxDynamicSharedMemorySize,
                         SMEM_BYTES);
    int grid = (M_ROWS / BM) * (N_DIM / BN);   // 8192
    qgemm_kernel<<<grid, 128, SMEM_BYTES>>>(scale, bias, out);
}

// round 10
// speedup vs baseline: 1.3409x; 1.3409x over previous
#include <cuda_runtime.h>
#include <cuda_fp16.h>
#include <cstdint>

// ---------------------------------------------------------------------------
// y[8192,16384] = x[8192,4096] @ dequant(W[4096,16384]) * scale + bias
// Weight arrives as int32 (harness dtype set is f32/i32/bf16).
// R10: fill issue interleaved into the ks-loop (no tensor-idle block at the
//      barrier edge); converts fused into one kernel (2 launches/call so the
//      ncu -s 5 capture lands on the GEMM).
// Base: 128x128 tile, 128 threads (4 warps @ 64x64), 3-stage BK=64, 2 CTAs/SM.
// ---------------------------------------------------------------------------
static constexpr int M_ROWS = 8192;
static constexpr int K_DIM  = 4096;
static constexpr int N_DIM  = 16384;

static constexpr int BM = 128;
static constexpr int BN = 128;
static constexpr int BK = 64;
static constexpr int STAGES = 3;
static constexpr int NITER  = K_DIM / BK;     // 64
static constexpr int KSTEPS = BK / 16;        // 4

static constexpr int A_LD = BK + 8;           // 72 halves = 144 B
static constexpr int B_LD = BK + 8;
static constexpr int A_ST = BM * A_LD;        // 9216 halves
static constexpr int B_ST = BN * B_LD;        // 9216 halves
static constexpr int STG  = A_ST + B_ST;      // 18432 halves = 36864 B
static constexpr int SMEM_BYTES = STAGES * STG * 2;   // 110592 B -> 2 CTAs/SM

__device__ __half g_xh[(size_t)M_ROWS * K_DIM];   //  64 MiB  [M][K]
__device__ __half g_wh[(size_t)N_DIM * K_DIM];    // 128 MiB  [N][K]

// ---------------------------------------------------------------------------
__device__ __forceinline__ uint32_t smem_u32(const void* p) {
    uint32_t a;
    asm("{ .reg .u64 t; cvta.to.shared.u64 t, %1; cvt.u32.u64 %0, t; }" : "=r"(a) : "l"(p));
    return a;
}

__device__ __forceinline__ void cp16(uint32_t dst, const void* src) {
    asm volatile("cp.async.cg.shared.global [%0], [%1], 16;" :: "r"(dst), "l"(src));
}

#define CP_COMMIT() asm volatile("cp.async.commit_group;" ::: "memory")

__device__ __forceinline__ void ldsm4(uint32_t* r, uint32_t addr) {
    asm volatile("ldmatrix.sync.aligned.m8n8.x4.shared.b16 {%0,%1,%2,%3}, [%4];"
                 : "=r"(r[0]), "=r"(r[1]), "=r"(r[2]), "=r"(r[3]) : "r"(addr));
}

__device__ __forceinline__ void mma16816(float* d, const uint32_t* a, uint32_t b0, uint32_t b1) {
    asm volatile(
        "mma.sync.aligned.m16n8k16.row.col.f32.f16.f16.f32 "
        "{%0,%1,%2,%3}, {%4,%5,%6,%7}, {%8,%9}, {%0,%1,%2,%3};"
        : "+f"(d[0]), "+f"(d[1]), "+f"(d[2]), "+f"(d[3])
        : "r"(a[0]), "r"(a[1]), "r"(a[2]), "r"(a[3]), "r"(b0), "r"(b1));
}

// ---------------------------------------------------------------------------
// Fused prep kernel: blocks [0, XB) convert x; blocks [XB, XB+WBX*WBY) do
// the W int32->fp16 [K,N]->[N,K] 32x32 transpose. 256 threads everywhere.
// ---------------------------------------------------------------------------
static constexpr int XB  = (M_ROWS * K_DIM / 4) / 256;   // 32768 blocks
static constexpr int WBX = N_DIM / 32;                   // 512
static constexpr int WBY = K_DIM / 32;                   // 128

__global__ void cvt_fused_kernel(const float4* __restrict__ x,
                                 const int* __restrict__ w,
                                 __half2* __restrict__ xh,
                                 __half* __restrict__ wh) {
    if (blockIdx.x < XB) {
        int i = blockIdx.x * 256 + threadIdx.x;
        float4 v = x[i];
        xh[2 * i]     = __floats2half2_rn(v.x, v.y);
        xh[2 * i + 1] = __floats2half2_rn(v.z, v.w);
    } else {
        __shared__ int t[32][33];
        int wb = blockIdx.x - XB;
        int n0 = (wb % WBX) * 32, k0 = (wb / WBX) * 32;
        int tx = threadIdx.x & 31, ty = threadIdx.x >> 5;   // 32 x 8
        #pragma unroll
        for (int i = ty; i < 32; i += 8)
            t[i][tx] = w[(size_t)(k0 + i) * N_DIM + n0 + tx];
        __syncthreads();
        #pragma unroll
        for (int i = ty; i < 32; i += 8)
            wh[(size_t)(n0 + i) * K_DIM + k0 + tx] = __int2half_rn(t[tx][i]);
    }
}

// ---------------------------------------------------------------------------
// Main GEMM
// ---------------------------------------------------------------------------
__global__ void __launch_bounds__(128, 2) qgemm_kernel(
    const float* __restrict__ scale,
    const float* __restrict__ bias,
    float* __restrict__ out)
{
    extern __shared__ __align__(16) char smem_raw[];
    const uint32_t sb = smem_u32(smem_raw);
    const int tid = threadIdx.x;
    const int wid = tid >> 5;
    const int lid = tid & 31;

    const int bid = blockIdx.x;
    const int group  = bid >> 9;
    const int within = bid & 511;
    const int nt = (group << 3) | (within & 7);
    const int mt = within >> 3;
    const int m0 = mt * BM;
    const int n0 = nt * BN;

    const __half* __restrict__ xh = g_xh;
    const __half* __restrict__ wh = g_wh;

    // Per-thread fill addressing (constant across iters except k0/base)
    const int fa_row = tid >> 3, fa_cc = (tid & 7);         // within 128x8 grid
    const __half* xrow = xh + (size_t)(m0 + fa_row) * K_DIM + fa_cc * 8;
    const __half* wrow = wh + (size_t)(n0 + fa_row) * K_DIM + fa_cc * 8;
    const uint32_t a_dst0 = (uint32_t)(fa_row * A_LD + fa_cc * 8) * 2;
    const uint32_t b_dst0 = (uint32_t)(A_ST + fa_row * B_LD + fa_cc * 8) * 2;

    // One quarter of a stage fill: 2 A-chunks + 2 B-chunks per thread.
    // part p covers rows [p*32, p*32+32) of A and B (via ci = tid + 128*j).
    auto fill_part = [&](int it, int p) {
        const int k0 = it * BK;
        const uint32_t base = sb + (uint32_t)(it % STAGES) * (STG * 2);
        #pragma unroll
        for (int j = 0; j < 2; ++j) {
            int r = (p * 2 + j) * 16;   // row offset: 128*j' >> 3 = 16 rows per 128 ci
            cp16(base + a_dst0 + (uint32_t)(r * A_LD) * 2, xrow + (size_t)r * K_DIM + k0);
            cp16(base + b_dst0 + (uint32_t)(r * B_LD) * 2, wrow + (size_t)r * K_DIM + k0);
        }
    };

    const int wmb = (wid & 1) * 64;
    const int wnb = (wid >> 1) * 64;

    float acc[4][8][4];
    #pragma unroll
    for (int i = 0; i < 4; ++i)
        #pragma unroll
        for (int j = 0; j < 8; ++j)
            #pragma unroll
            for (int k = 0; k < 4; ++k) acc[i][j][k] = 0.0f;

    // Prologue: stages 0 and 1, full fills
    #pragma unroll
    for (int s = 0; s < 2; ++s) {
        #pragma unroll
        for (int p = 0; p < KSTEPS; ++p) fill_part(s, p);
        CP_COMMIT();
    }

    const int a_row_lane = lid & 15;
    const int a_col_lane = (lid >> 4) * 8;
    const int b_row_lane = (lid & 7) | ((lid >> 4) << 3);
    const int b_col_lane = ((lid >> 3) & 1) * 8;

    const uint32_t a_off = (uint32_t)((wmb + a_row_lane) * A_LD + a_col_lane) * 2;
    const uint32_t b_off = (uint32_t)(A_ST + (wnb + b_row_lane) * B_LD + b_col_lane) * 2;

    #pragma unroll 1
    for (int it = 0; it < NITER; ++it) {
        asm volatile("cp.async.wait_group 1;" ::: "memory");
        __syncthreads();
        const bool do_fill = (it + 2 < NITER);
        const uint32_t base = sb + (uint32_t)(it % STAGES) * (STG * 2);

        #pragma unroll
        for (int ks = 0; ks < KSTEPS; ++ks) {
            uint32_t a[4][4], b[4][4];
            #pragma unroll
            for (int mf = 0; mf < 4; ++mf)
                ldsm4(a[mf], base + a_off + (uint32_t)(mf * 16 * A_LD + ks * 16) * 2);
            #pragma unroll
            for (int nf2 = 0; nf2 < 4; ++nf2)
                ldsm4(b[nf2], base + b_off + (uint32_t)(nf2 * 16 * B_LD + ks * 16) * 2);
            // issue a quarter of the it+2 fill in the ldsm->mma latency shadow
            if (do_fill) fill_part(it + 2, ks);
            #pragma unroll
            for (int mf = 0; mf < 4; ++mf) {
                #pragma unroll
                for (int nf2 = 0; nf2 < 4; ++nf2) {
                    mma16816(acc[mf][nf2 * 2],     a[mf], b[nf2][0], b[nf2][1]);
                    mma16816(acc[mf][nf2 * 2 + 1], a[mf], b[nf2][2], b[nf2][3]);
                }
            }
        }
        CP_COMMIT();   // exactly one commit per iteration (tail-safe)
    }

    // ---- Epilogue: fused scale/bias, float2 stores ----
    const int ncol0 = n0 + wnb;
    float2 sc[8], bi[8];
    #pragma unroll
    for (int nf = 0; nf < 8; ++nf) {
        int c = nf * 8 + (lid & 3) * 2;
        sc[nf] = *reinterpret_cast<const float2*>(scale + ncol0 + c);
        bi[nf] = *reinterpret_cast<const float2*>(bias + ncol0 + c);
    }
    #pragma unroll
    for (int mf = 0; mf < 4; ++mf) {
        int r0 = m0 + wmb + mf * 16 + (lid >> 2);
        float* out0 = out + (size_t)r0 * N_DIM + ncol0;
        float* out1 = out0 + (size_t)8 * N_DIM;
        #pragma unroll
        for (int nf = 0; nf < 8; ++nf) {
            int c = nf * 8 + (lid & 3) * 2;
            float2 v0 = make_float2(fmaf(acc[mf][nf][0], sc[nf].x, bi[nf].x),
                                    fmaf(acc[mf][nf][1], sc[nf].y, bi[nf].y));
            float2 v1 = make_float2(fmaf(acc[mf][nf][2], sc[nf].x, bi[nf].x),
                                    fmaf(acc[mf][nf][3], sc[nf].y, bi[nf].y));
            *reinterpret_cast<float2*>(out0 + c) = v0;
            *reinterpret_cast<float2*>(out1 + c) = v1;
        }
    }
}

// ---------------------------------------------------------------------------
// Host launch — inputs identified by element count.
// ---------------------------------------------------------------------------
extern "C" void kernel_launch(void* const* d_in, const int* in_sizes, int n_in,
                              void* d_out, int out_size) {
    int xi = 0, wi = 1, sm1 = -1, sm2 = -1;
    for (int i = 0; i < 4; ++i) {
        if (in_sizes[i] == M_ROWS * K_DIM)      xi = i;
        else if (in_sizes[i] == K_DIM * N_DIM)  wi = i;
        else if (sm1 < 0)                       sm1 = i;
        else                                    sm2 = i;
    }
    int si, bi2;
    if (xi < sm1) { si = sm1; bi2 = sm2; }   // dict order: x, w, scale, bias
    else          { bi2 = sm1; si = sm2; }

    const float* x     = (const float*)d_in[xi];
    const int*   w     = (const int*)d_in[wi];
    const float* scale = (const float*)d_in[si];
    const float* bias  = (const float*)d_in[bi2];
    float*       out   = (float*)d_out;

    void* xh = nullptr; cudaGetSymbolAddress(&xh, g_xh);
    void* wh = nullptr; cudaGetSymbolAddress(&wh, g_wh);

    cvt_fused_kernel<<<XB + WBX * WBY, 256>>>((const float4*)x, w,
                                              (__half2*)xh, (__half*)wh);

    cudaFuncSetAttribute(qgemm_kernel, cudaFuncAttributeMaxDynamicSharedMemorySize,
                         SMEM_BYTES);
    int grid = (M_ROWS / BM) * (N_DIM / BN);   // 8192
    qgemm_kernel<<<grid, 128, SMEM_BYTES>>>(scale, bias, out);
}

// round 11
// speedup vs baseline: 1.3612x; 1.0151x over previous
#include <cuda_runtime.h>
#include <cuda_fp16.h>
#include <cstdint>

// ---------------------------------------------------------------------------
// y[8192,16384] = x[8192,4096] @ dequant(W[4096,16384]) * scale + bias
// Weight arrives as int32 (harness dtype set is f32/i32/bf16).
// R11: rotating stage bases (no %STAGES math), early commit (DMA starts one
//      MMA block sooner), pointer-hoisted fill addressing.
// Base: 128x128 tile, 128 threads (4 warps @ 64x64), 3-stage BK=64, 2 CTAs/SM.
// ---------------------------------------------------------------------------
static constexpr int M_ROWS = 8192;
static constexpr int K_DIM  = 4096;
static constexpr int N_DIM  = 16384;

static constexpr int BM = 128;
static constexpr int BN = 128;
static constexpr int BK = 64;
static constexpr int STAGES = 3;
static constexpr int NITER  = K_DIM / BK;     // 64
static constexpr int KSTEPS = BK / 16;        // 4

static constexpr int A_LD = BK + 8;           // 72 halves = 144 B
static constexpr int B_LD = BK + 8;
static constexpr int A_ST = BM * A_LD;        // 9216 halves
static constexpr int B_ST = BN * B_LD;        // 9216 halves
static constexpr int STG  = A_ST + B_ST;      // 18432 halves = 36864 B
static constexpr int SMEM_BYTES = STAGES * STG * 2;   // 110592 B -> 2 CTAs/SM

__device__ __half g_xh[(size_t)M_ROWS * K_DIM];   //  64 MiB  [M][K]
__device__ __half g_wh[(size_t)N_DIM * K_DIM];    // 128 MiB  [N][K]

// ---------------------------------------------------------------------------
__device__ __forceinline__ uint32_t smem_u32(const void* p) {
    uint32_t a;
    asm("{ .reg .u64 t; cvta.to.shared.u64 t, %1; cvt.u32.u64 %0, t; }" : "=r"(a) : "l"(p));
    return a;
}

__device__ __forceinline__ void cp16(uint32_t dst, const void* src) {
    asm volatile("cp.async.cg.shared.global [%0], [%1], 16;" :: "r"(dst), "l"(src));
}

#define CP_COMMIT() asm volatile("cp.async.commit_group;" ::: "memory")

__device__ __forceinline__ void ldsm4(uint32_t* r, uint32_t addr) {
    asm volatile("ldmatrix.sync.aligned.m8n8.x4.shared.b16 {%0,%1,%2,%3}, [%4];"
                 : "=r"(r[0]), "=r"(r[1]), "=r"(r[2]), "=r"(r[3]) : "r"(addr));
}

__device__ __forceinline__ void mma16816(float* d, const uint32_t* a, uint32_t b0, uint32_t b1) {
    asm volatile(
        "mma.sync.aligned.m16n8k16.row.col.f32.f16.f16.f32 "
        "{%0,%1,%2,%3}, {%4,%5,%6,%7}, {%8,%9}, {%0,%1,%2,%3};"
        : "+f"(d[0]), "+f"(d[1]), "+f"(d[2]), "+f"(d[3])
        : "r"(a[0]), "r"(a[1]), "r"(a[2]), "r"(a[3]), "r"(b0), "r"(b1));
}

// ---------------------------------------------------------------------------
// Fused prep kernel
// ---------------------------------------------------------------------------
static constexpr int XB  = (M_ROWS * K_DIM / 4) / 256;   // 32768 blocks
static constexpr int WBX = N_DIM / 32;                   // 512
static constexpr int WBY = K_DIM / 32;                   // 128

__global__ void cvt_fused_kernel(const float4* __restrict__ x,
                                 const int* __restrict__ w,
                                 __half2* __restrict__ xh,
                                 __half* __restrict__ wh) {
    if (blockIdx.x < XB) {
        int i = blockIdx.x * 256 + threadIdx.x;
        float4 v = x[i];
        xh[2 * i]     = __floats2half2_rn(v.x, v.y);
        xh[2 * i + 1] = __floats2half2_rn(v.z, v.w);
    } else {
        __shared__ int t[32][33];
        int wb = blockIdx.x - XB;
        int n0 = (wb % WBX) * 32, k0 = (wb / WBX) * 32;
        int tx = threadIdx.x & 31, ty = threadIdx.x >> 5;
        #pragma unroll
        for (int i = ty; i < 32; i += 8)
            t[i][tx] = w[(size_t)(k0 + i) * N_DIM + n0 + tx];
        __syncthreads();
        #pragma unroll
        for (int i = ty; i < 32; i += 8)
            wh[(size_t)(n0 + i) * K_DIM + k0 + tx] = __int2half_rn(t[tx][i]);
    }
}

// ---------------------------------------------------------------------------
// Main GEMM
// ---------------------------------------------------------------------------
__global__ void __launch_bounds__(128, 2) qgemm_kernel(
    const float* __restrict__ scale,
    const float* __restrict__ bias,
    float* __restrict__ out)
{
    extern __shared__ __align__(16) char smem_raw[];
    const uint32_t sb = smem_u32(smem_raw);
    const int tid = threadIdx.x;
    const int wid = tid >> 5;
    const int lid = tid & 31;

    const int bid = blockIdx.x;
    const int group  = bid >> 9;
    const int within = bid & 511;
    const int nt = (group << 3) | (within & 7);
    const int mt = within >> 3;
    const int m0 = mt * BM;
    const int n0 = nt * BN;

    const __half* __restrict__ xh = g_xh;
    const __half* __restrict__ wh = g_wh;

    // Per-thread fill addressing
    const int fa_row = tid >> 3, fa_cc = (tid & 7);
    const __half* xrow = xh + (size_t)(m0 + fa_row) * K_DIM + fa_cc * 8;
    const __half* wrow = wh + (size_t)(n0 + fa_row) * K_DIM + fa_cc * 8;
    const uint32_t a_dst0 = (uint32_t)(fa_row * A_LD + fa_cc * 8) * 2;
    const uint32_t b_dst0 = (uint32_t)(A_ST + fa_row * B_LD + fa_cc * 8) * 2;

    const int wmb = (wid & 1) * 64;
    const int wnb = (wid >> 1) * 64;

    float acc[4][8][4];
    #pragma unroll
    for (int i = 0; i < 4; ++i)
        #pragma unroll
        for (int j = 0; j < 8; ++j)
            #pragma unroll
            for (int k = 0; k < 4; ++k) acc[i][j][k] = 0.0f;

    // Rotating stage bases
    uint32_t s0 = sb;
    uint32_t s1 = sb + (uint32_t)(STG * 2);
    uint32_t s2 = sb + (uint32_t)(2 * STG * 2);

    // Prologue: full fills of stages 0 and 1
    #pragma unroll
    for (int s = 0; s < 2; ++s) {
        const uint32_t base = (s == 0) ? s0 : s1;
        const int k0 = s * BK;
        #pragma unroll
        for (int p = 0; p < 2 * KSTEPS; ++p) {
            int r = p * 16;
            cp16(base + a_dst0 + (uint32_t)(r * A_LD) * 2, xrow + (size_t)r * K_DIM + k0);
            cp16(base + b_dst0 + (uint32_t)(r * B_LD) * 2, wrow + (size_t)r * K_DIM + k0);
        }
        CP_COMMIT();
    }

    const int a_row_lane = lid & 15;
    const int a_col_lane = (lid >> 4) * 8;
    const int b_row_lane = (lid & 7) | ((lid >> 4) << 3);
    const int b_col_lane = ((lid >> 3) & 1) * 8;

    const uint32_t a_off = (uint32_t)((wmb + a_row_lane) * A_LD + a_col_lane) * 2;
    const uint32_t b_off = (uint32_t)(A_ST + (wnb + b_row_lane) * B_LD + b_col_lane) * 2;

    int kf = 2 * BK;   // fill k-offset for stage it+2

    #pragma unroll 1
    for (int it = 0; it < NITER; ++it) {
        asm volatile("cp.async.wait_group 1;" ::: "memory");
        __syncthreads();
        const bool do_fill = (it + 2 < NITER);
        const __half* xp = xrow + kf;
        const __half* wp = wrow + kf;

        #pragma unroll
        for (int ks = 0; ks < KSTEPS; ++ks) {
            uint32_t a[4][4], b[4][4];
            #pragma unroll
            for (int mf = 0; mf < 4; ++mf)
                ldsm4(a[mf], s0 + a_off + (uint32_t)(mf * 16 * A_LD + ks * 16) * 2);
            #pragma unroll
            for (int nf2 = 0; nf2 < 4; ++nf2)
                ldsm4(b[nf2], s0 + b_off + (uint32_t)(nf2 * 16 * B_LD + ks * 16) * 2);
            // quarter of stage it+2 fill, hidden in the ldsm->mma shadow
            if (do_fill) {
                #pragma unroll
                for (int j = 0; j < 2; ++j) {
                    int r = (ks * 2 + j) * 16;
                    cp16(s2 + a_dst0 + (uint32_t)(r * A_LD) * 2, xp + (size_t)r * K_DIM);
                    cp16(s2 + b_dst0 + (uint32_t)(r * B_LD) * 2, wp + (size_t)r * K_DIM);
                }
            }
            if (ks == KSTEPS - 1) CP_COMMIT();   // commit before the last MMA block
            #pragma unroll
            for (int mf = 0; mf < 4; ++mf) {
                #pragma unroll
                for (int nf2 = 0; nf2 < 4; ++nf2) {
                    mma16816(acc[mf][nf2 * 2],     a[mf], b[nf2][0], b[nf2][1]);
                    mma16816(acc[mf][nf2 * 2 + 1], a[mf], b[nf2][2], b[nf2][3]);
                }
            }
        }
        // rotate stages, advance fill k
        uint32_t t = s0; s0 = s1; s1 = s2; s2 = t;
        kf += BK;
    }

    // ---- Epilogue: fused scale/bias, float2 stores ----
    const int ncol0 = n0 + wnb;
    float2 sc[8], bi[8];
    #pragma unroll
    for (int nf = 0; nf < 8; ++nf) {
        int c = nf * 8 + (lid & 3) * 2;
        sc[nf] = *reinterpret_cast<const float2*>(scale + ncol0 + c);
        bi[nf] = *reinterpret_cast<const float2*>(bias + ncol0 + c);
    }
    #pragma unroll
    for (int mf = 0; mf < 4; ++mf) {
        int r0 = m0 + wmb + mf * 16 + (lid >> 2);
        float* out0 = out + (size_t)r0 * N_DIM + ncol0;
        float* out1 = out0 + (size_t)8 * N_DIM;
        #pragma unroll
        for (int nf = 0; nf < 8; ++nf) {
            int c = nf * 8 + (lid & 3) * 2;
            float2 v0 = make_float2(fmaf(acc[mf][nf][0], sc[nf].x, bi[nf].x),
                                    fmaf(acc[mf][nf][1], sc[nf].y, bi[nf].y));
            float2 v1 = make_float2(fmaf(acc[mf][nf][2], sc[nf].x, bi[nf].x),
                                    fmaf(acc[mf][nf][3], sc[nf].y, bi[nf].y));
            *reinterpret_cast<float2*>(out0 + c) = v0;
            *reinterpret_cast<float2*>(out1 + c) = v1;
        }
    }
}

// ---------------------------------------------------------------------------
// Host launch — inputs identified by element count.
// ---------------------------------------------------------------------------
extern "C" void kernel_launch(void* const* d_in, const int* in_sizes, int n_in,
                              void* d_out, int out_size) {
    int xi = 0, wi = 1, sm1 = -1, sm2 = -1;
    for (int i = 0; i < 4; ++i) {
        if (in_sizes[i] == M_ROWS * K_DIM)      xi = i;
        else if (in_sizes[i] == K_DIM * N_DIM)  wi = i;
        else if (sm1 < 0)                       sm1 = i;
        else                                    sm2 = i;
    }
    int si, bi2;
    if (xi < sm1) { si = sm1; bi2 = sm2; }   // dict order: x, w, scale, bias
    else          { bi2 = sm1; si = sm2; }

    const float* x     = (const float*)d_in[xi];
    const int*   w     = (const int*)d_in[wi];
    const float* scale = (const float*)d_in[si];
    const float* bias  = (const float*)d_in[bi2];
    float*       out   = (float*)d_out;

    void* xh = nullptr; cudaGetSymbolAddress(&xh, g_xh);
    void* wh = nullptr; cudaGetSymbolAddress(&wh, g_wh);

    cvt_fused_kernel<<<XB + WBX * WBY, 256>>>((const float4*)x, w,
                                              (__half2*)xh, (__half*)wh);

    cudaFuncSetAttribute(qgemm_kernel, cudaFuncAttributeMaxDynamicSharedMemorySize,
                         SMEM_BYTES);
    int grid = (M_ROWS / BM) * (N_DIM / BN);   // 8192
    qgemm_kernel<<<grid, 128, SMEM_BYTES>>>(scale, bias, out);
}

// round 12
// speedup vs baseline: 1.3753x; 1.0103x over previous
#include <cuda_runtime.h>
#include <cuda_fp16.h>
#include <cstdint>

// ---------------------------------------------------------------------------
// y[8192,16384] = x[8192,4096] @ dequant(W[4096,16384]) * scale + bias
// Weight arrives as int32 (harness dtype set is f32/i32/bf16).
// R12: wait_group decoupled from __syncthreads (wait drains under the MMA
//      tail), streaming epilogue stores, 128B-coalesced W transpose.
// Base: 128x128 tile, 128 threads (4 warps @ 64x64), 3-stage BK=64, 2 CTAs/SM.
// ---------------------------------------------------------------------------
static constexpr int M_ROWS = 8192;
static constexpr int K_DIM  = 4096;
static constexpr int N_DIM  = 16384;

static constexpr int BM = 128;
static constexpr int BN = 128;
static constexpr int BK = 64;
static constexpr int STAGES = 3;
static constexpr int NITER  = K_DIM / BK;     // 64
static constexpr int KSTEPS = BK / 16;        // 4

static constexpr int A_LD = BK + 8;           // 72 halves = 144 B
static constexpr int B_LD = BK + 8;
static constexpr int A_ST = BM * A_LD;        // 9216 halves
static constexpr int B_ST = BN * B_LD;        // 9216 halves
static constexpr int STG  = A_ST + B_ST;      // 18432 halves = 36864 B
static constexpr int SMEM_BYTES = STAGES * STG * 2;   // 110592 B -> 2 CTAs/SM

__device__ __half g_xh[(size_t)M_ROWS * K_DIM];   //  64 MiB  [M][K]
__device__ __half g_wh[(size_t)N_DIM * K_DIM];    // 128 MiB  [N][K]

// ---------------------------------------------------------------------------
__device__ __forceinline__ uint32_t smem_u32(const void* p) {
    uint32_t a;
    asm("{ .reg .u64 t; cvta.to.shared.u64 t, %1; cvt.u32.u64 %0, t; }" : "=r"(a) : "l"(p));
    return a;
}

__device__ __forceinline__ void cp16(uint32_t dst, const void* src) {
    asm volatile("cp.async.cg.shared.global [%0], [%1], 16;" :: "r"(dst), "l"(src));
}

#define CP_COMMIT() asm volatile("cp.async.commit_group;" ::: "memory")

__device__ __forceinline__ void ldsm4(uint32_t* r, uint32_t addr) {
    asm volatile("ldmatrix.sync.aligned.m8n8.x4.shared.b16 {%0,%1,%2,%3}, [%4];"
                 : "=r"(r[0]), "=r"(r[1]), "=r"(r[2]), "=r"(r[3]) : "r"(addr));
}

__device__ __forceinline__ void mma16816(float* d, const uint32_t* a, uint32_t b0, uint32_t b1) {
    asm volatile(
        "mma.sync.aligned.m16n8k16.row.col.f32.f16.f16.f32 "
        "{%0,%1,%2,%3}, {%4,%5,%6,%7}, {%8,%9}, {%0,%1,%2,%3};"
        : "+f"(d[0]), "+f"(d[1]), "+f"(d[2]), "+f"(d[3])
        : "r"(a[0]), "r"(a[1]), "r"(a[2]), "r"(a[3]), "r"(b0), "r"(b1));
}

__device__ __forceinline__ void stcs2(float* p, float vx, float vy) {
    asm volatile("st.global.cs.v2.f32 [%0], {%1, %2};" :: "l"(p), "f"(vx), "f"(vy) : "memory");
}

// ---------------------------------------------------------------------------
// Fused prep kernel: x convert blocks, then W transpose blocks (64k x 32n,
// 128B-coalesced reads and half2 writes).
// ---------------------------------------------------------------------------
static constexpr int XB   = (M_ROWS * K_DIM / 4) / 256;   // 32768 blocks
static constexpr int WBX  = N_DIM / 32;                   // 512
static constexpr int WBY  = K_DIM / 64;                   // 64

__global__ void cvt_fused_kernel(const float4* __restrict__ x,
                                 const int* __restrict__ w,
                                 __half2* __restrict__ xh,
                                 __half* __restrict__ wh) {
    if (blockIdx.x < XB) {
        int i = blockIdx.x * 256 + threadIdx.x;
        float4 v = x[i];
        xh[2 * i]     = __floats2half2_rn(v.x, v.y);
        xh[2 * i + 1] = __floats2half2_rn(v.z, v.w);
    } else {
        __shared__ int t[64][33];
        int wb = blockIdx.x - XB;
        int n0 = (wb % WBX) * 32;
        int k0 = (wb / WBX) * 64;
        int tx = threadIdx.x & 31, ty = threadIdx.x >> 5;   // 32 x 8
        #pragma unroll
        for (int j = 0; j < 8; ++j) {
            int k = ty + 8 * j;
            t[k][tx] = w[(size_t)(k0 + k) * N_DIM + n0 + tx];
        }
        __syncthreads();
        #pragma unroll
        for (int j = 0; j < 4; ++j) {
            int i = ty + 8 * j;   // n row 0..31
            __half2 v = __halves2half2(__int2half_rn(t[2 * tx][i]),
                                       __int2half_rn(t[2 * tx + 1][i]));
            *reinterpret_cast<__half2*>(wh + (size_t)(n0 + i) * K_DIM + k0 + 2 * tx) = v;
        }
    }
}

// ---------------------------------------------------------------------------
// Main GEMM
// ---------------------------------------------------------------------------
__global__ void __launch_bounds__(128, 2) qgemm_kernel(
    const float* __restrict__ scale,
    const float* __restrict__ bias,
    float* __restrict__ out)
{
    extern __shared__ __align__(16) char smem_raw[];
    const uint32_t sb = smem_u32(smem_raw);
    const int tid = threadIdx.x;
    const int wid = tid >> 5;
    const int lid = tid & 31;

    const int bid = blockIdx.x;
    const int group  = bid >> 9;
    const int within = bid & 511;
    const int nt = (group << 3) | (within & 7);
    const int mt = within >> 3;
    const int m0 = mt * BM;
    const int n0 = nt * BN;

    const __half* __restrict__ xh = g_xh;
    const __half* __restrict__ wh = g_wh;

    // Per-thread fill addressing
    const int fa_row = tid >> 3, fa_cc = (tid & 7);
    const __half* xrow = xh + (size_t)(m0 + fa_row) * K_DIM + fa_cc * 8;
    const __half* wrow = wh + (size_t)(n0 + fa_row) * K_DIM + fa_cc * 8;
    const uint32_t a_dst0 = (uint32_t)(fa_row * A_LD + fa_cc * 8) * 2;
    const uint32_t b_dst0 = (uint32_t)(A_ST + fa_row * B_LD + fa_cc * 8) * 2;

    const int wmb = (wid & 1) * 64;
    const int wnb = (wid >> 1) * 64;

    float acc[4][8][4];
    #pragma unroll
    for (int i = 0; i < 4; ++i)
        #pragma unroll
        for (int j = 0; j < 8; ++j)
            #pragma unroll
            for (int k = 0; k < 4; ++k) acc[i][j][k] = 0.0f;

    // Rotating stage bases
    uint32_t s0 = sb;
    uint32_t s1 = sb + (uint32_t)(STG * 2);
    uint32_t s2 = sb + (uint32_t)(2 * STG * 2);

    // Prologue: full fills of stages 0 and 1
    #pragma unroll
    for (int s = 0; s < 2; ++s) {
        const uint32_t base = (s == 0) ? s0 : s1;
        const int k0 = s * BK;
        #pragma unroll
        for (int p = 0; p < 2 * KSTEPS; ++p) {
            int r = p * 16;
            cp16(base + a_dst0 + (uint32_t)(r * A_LD) * 2, xrow + (size_t)r * K_DIM + k0);
            cp16(base + b_dst0 + (uint32_t)(r * B_LD) * 2, wrow + (size_t)r * K_DIM + k0);
        }
        CP_COMMIT();
    }

    const int a_row_lane = lid & 15;
    const int a_col_lane = (lid >> 4) * 8;
    const int b_row_lane = (lid & 7) | ((lid >> 4) << 3);
    const int b_col_lane = ((lid >> 3) & 1) * 8;

    const uint32_t a_off = (uint32_t)((wmb + a_row_lane) * A_LD + a_col_lane) * 2;
    const uint32_t b_off = (uint32_t)(A_ST + (wnb + b_row_lane) * B_LD + b_col_lane) * 2;

    int kf = 2 * BK;   // fill k-offset for stage it+2

    // Pre-loop: ensure this thread's stage-0 group is drained; the barrier at
    // the top of each iteration then publishes completions across threads.
    asm volatile("cp.async.wait_group 1;" ::: "memory");

    #pragma unroll 1
    for (int it = 0; it < NITER; ++it) {
        __syncthreads();
        const bool do_fill = (it + 2 < NITER);
        const __half* xp = xrow + kf;
        const __half* wp = wrow + kf;

        #pragma unroll
        for (int ks = 0; ks < KSTEPS; ++ks) {
            uint32_t a[4][4], b[4][4];
            #pragma unroll
            for (int mf = 0; mf < 4; ++mf)
                ldsm4(a[mf], s0 + a_off + (uint32_t)(mf * 16 * A_LD + ks * 16) * 2);
            #pragma unroll
            for (int nf2 = 0; nf2 < 4; ++nf2)
                ldsm4(b[nf2], s0 + b_off + (uint32_t)(nf2 * 16 * B_LD + ks * 16) * 2);
            // quarter of stage it+2 fill, hidden in the ldsm->mma shadow
            if (do_fill) {
                #pragma unroll
                for (int j = 0; j < 2; ++j) {
                    int r = (ks * 2 + j) * 16;
                    cp16(s2 + a_dst0 + (uint32_t)(r * A_LD) * 2, xp + (size_t)r * K_DIM);
                    cp16(s2 + b_dst0 + (uint32_t)(r * B_LD) * 2, wp + (size_t)r * K_DIM);
                }
            }
            if (ks == KSTEPS - 1) CP_COMMIT();   // one commit per iteration
            #pragma unroll
            for (int mf = 0; mf < 4; ++mf) {
                #pragma unroll
                for (int nf2 = 0; nf2 < 4; ++nf2) {
                    mma16816(acc[mf][nf2 * 2],     a[mf], b[nf2][0], b[nf2][1]);
                    mma16816(acc[mf][nf2 * 2 + 1], a[mf], b[nf2][2], b[nf2][3]);
                }
            }
        }
        // Drain own next-stage group while the tail MMA block executes.
        asm volatile("cp.async.wait_group 1;" ::: "memory");
        uint32_t t = s0; s0 = s1; s1 = s2; s2 = t;
        kf += BK;
    }

    // ---- Epilogue: fused scale/bias, streaming float2 stores ----
    const int ncol0 = n0 + wnb;
    float2 sc[8], bi[8];
    #pragma unroll
    for (int nf = 0; nf < 8; ++nf) {
        int c = nf * 8 + (lid & 3) * 2;
        sc[nf] = *reinterpret_cast<const float2*>(scale + ncol0 + c);
        bi[nf] = *reinterpret_cast<const float2*>(bias + ncol0 + c);
    }
    #pragma unroll
    for (int mf = 0; mf < 4; ++mf) {
        int r0 = m0 + wmb + mf * 16 + (lid >> 2);
        float* out0 = out + (size_t)r0 * N_DIM + ncol0;
        float* out1 = out0 + (size_t)8 * N_DIM;
        #pragma unroll
        for (int nf = 0; nf < 8; ++nf) {
            int c = nf * 8 + (lid & 3) * 2;
            stcs2(out0 + c, fmaf(acc[mf][nf][0], sc[nf].x, bi[nf].x),
                            fmaf(acc[mf][nf][1], sc[nf].y, bi[nf].y));
            stcs2(out1 + c, fmaf(acc[mf][nf][2], sc[nf].x, bi[nf].x),
                            fmaf(acc[mf][nf][3], sc[nf].y, bi[nf].y));
        }
    }
}

// ---------------------------------------------------------------------------
// Host launch — inputs identified by element count.
// ---------------------------------------------------------------------------
extern "C" void kernel_launch(void* const* d_in, const int* in_sizes, int n_in,
                              void* d_out, int out_size) {
    int xi = 0, wi = 1, sm1 = -1, sm2 = -1;
    for (int i = 0; i < 4; ++i) {
        if (in_sizes[i] == M_ROWS * K_DIM)      xi = i;
        else if (in_sizes[i] == K_DIM * N_DIM)  wi = i;
        else if (sm1 < 0)                       sm1 = i;
        else                                    sm2 = i;
    }
    int si, bi2;
    if (xi < sm1) { si = sm1; bi2 = sm2; }   // dict order: x, w, scale, bias
    else          { bi2 = sm1; si = sm2; }

    const float* x     = (const float*)d_in[xi];
    const int*   w     = (const int*)d_in[wi];
    const float* scale = (const float*)d_in[si];
    const float* bias  = (const float*)d_in[bi2];
    float*       out   = (float*)d_out;

    void* xh = nullptr; cudaGetSymbolAddress(&xh, g_xh);
    void* wh = nullptr; cudaGetSymbolAddress(&wh, g_wh);

    cvt_fused_kernel<<<XB + WBX * WBY, 256>>>((const float4*)x, w,
                                              (__half2*)xh, (__half*)wh);

    cudaFuncSetAttribute(qgemm_kernel, cudaFuncAttributeMaxDynamicSharedMemorySize,
                         SMEM_BYTES);
    int grid = (M_ROWS / BM) * (N_DIM / BN);   // 8192
    qgemm_kernel<<<grid, 128, SMEM_BYTES>>>(scale, bias, out);
}